// round 3
// baseline (speedup 1.0000x reference)
#include <cuda_runtime.h>
#include <math.h>
#include <cstdint>

#define LSEQ   1024
#define NBATCH 64
#define NCH    64
#define NDIAG  2048
#define BIGC   1.0e10f
#define LOG2E  1.4426950408889634f
#define LN2F   0.6931471805599453f

/* Diagonal-major scratch: Ddiag[b][dd][i], dd = i + j (0-based). */
__device__ float g_Ddiag[(size_t)NBATCH * NDIAG * LSEQ];

__device__ __forceinline__ float ex2(float z) {
    float r; asm("ex2.approx.f32 %0, %1;" : "=f"(r) : "f"(z)); return r;
}
__device__ __forceinline__ float lg2(float z) {
    float r; asm("lg2.approx.f32 %0, %1;" : "=f"(r) : "f"(z)); return r;
}
__device__ __forceinline__ uint32_t f2tf32(float v) {
    uint32_t r; asm("cvt.rna.tf32.f32 %0, %1;" : "=r"(r) : "f"(v)); return r;
}
__device__ __forceinline__ uint32_t smem_u32(const void* p) {
    uint32_t a;
    asm("{ .reg .u64 t; cvta.to.shared.u64 t, %1; cvt.u32.u64 %0, t; }" : "=r"(a) : "l"(p));
    return a;
}

/* ------------------------------------------------------------------ */
/* Kernel A: D = (x2 + y2 - 2*x.y^T) * log2(e) via tf32 mma.sync,     */
/* written diagonal-major.                                             */
/* ------------------------------------------------------------------ */
__global__ void __launch_bounds__(256)
compute_D_kernel(const float* __restrict__ x, const float* __restrict__ y) {
    const int b  = blockIdx.y;
    const int ti = blockIdx.x >> 4;
    const int tj = blockIdx.x & 15;
    const int i0 = ti * 64, j0 = tj * 64;

    __shared__ float sbuf[2 * 64 * 68];    /* xs[64][68] | ys[64][68]; reused as Dt[64][66] */
    __shared__ float sx2[64], sy2[64];
    float* xs = sbuf;
    float* ys = sbuf + 64 * 68;

    const int tid = threadIdx.x;
    const float4* xb4 = (const float4*)(x + ((size_t)b * LSEQ + i0) * NCH);
    const float4* yb4 = (const float4*)(y + ((size_t)b * LSEQ + j0) * NCH);

#pragma unroll
    for (int k = 0; k < 4; k++) {
        int e = tid + 256 * k;
        int r = e >> 4, c4v = e & 15;
        *(float4*)&xs[r * 68 + c4v * 4] = xb4[r * 16 + c4v];
        *(float4*)&ys[r * 68 + c4v * 4] = yb4[r * 16 + c4v];
    }
    __syncthreads();

    if (tid < 64) {
        float s = 0.f;
#pragma unroll
        for (int c = 0; c < 64; c++) { float v = xs[tid * 68 + c]; s += v * v; }
        sx2[tid] = s;
    } else if (tid < 128) {
        int r = tid - 64;
        float s = 0.f;
#pragma unroll
        for (int c = 0; c < 64; c++) { float v = ys[r * 68 + c]; s += v * v; }
        sy2[r] = s;
    }
    __syncthreads();

    /* 8 warps: wr = warp&3 -> 16-row block, wc = warp>>2 -> 32-col block */
    const int wrp  = tid >> 5, lane = tid & 31;
    const int wr   = wrp & 3, wc = wrp >> 2;
    const int r4   = lane >> 2, c4 = lane & 3;
    const float* As = xs + (wr * 16) * 68;
    const float* Bs = ys + (wc * 32) * 68;

    float cc[4][4];
#pragma unroll
    for (int nt = 0; nt < 4; nt++)
#pragma unroll
        for (int q = 0; q < 4; q++) cc[nt][q] = 0.f;

#pragma unroll
    for (int k0 = 0; k0 < 64; k0 += 8) {
        uint32_t a0 = f2tf32(As[(r4)     * 68 + k0 + c4]);
        uint32_t a1 = f2tf32(As[(r4 + 8) * 68 + k0 + c4]);
        uint32_t a2 = f2tf32(As[(r4)     * 68 + k0 + c4 + 4]);
        uint32_t a3 = f2tf32(As[(r4 + 8) * 68 + k0 + c4 + 4]);
#pragma unroll
        for (int nt = 0; nt < 4; nt++) {
            uint32_t b0 = f2tf32(Bs[(nt * 8 + r4) * 68 + k0 + c4]);
            uint32_t b1 = f2tf32(Bs[(nt * 8 + r4) * 68 + k0 + c4 + 4]);
            asm volatile(
                "mma.sync.aligned.m16n8k8.row.col.f32.tf32.tf32.f32 "
                "{%0,%1,%2,%3}, {%4,%5,%6,%7}, {%8,%9}, {%0,%1,%2,%3};"
                : "+f"(cc[nt][0]), "+f"(cc[nt][1]), "+f"(cc[nt][2]), "+f"(cc[nt][3])
                : "r"(a0), "r"(a1), "r"(a2), "r"(a3), "r"(b0), "r"(b1));
        }
    }
    __syncthreads();                  /* xs/ys dead -> reuse as Dt */

    float* Dt = sbuf;                 /* [64][66] */
    const int row0 = wr * 16 + r4;
#pragma unroll
    for (int nt = 0; nt < 4; nt++) {
        int colb = wc * 32 + nt * 8 + 2 * c4;
        Dt[row0 * 66 + colb]           = (sx2[row0]     + sy2[colb]     - 2.0f * cc[nt][0]) * LOG2E;
        Dt[row0 * 66 + colb + 1]       = (sx2[row0]     + sy2[colb + 1] - 2.0f * cc[nt][1]) * LOG2E;
        Dt[(row0 + 8) * 66 + colb]     = (sx2[row0 + 8] + sy2[colb]     - 2.0f * cc[nt][2]) * LOG2E;
        Dt[(row0 + 8) * 66 + colb + 1] = (sx2[row0 + 8] + sy2[colb + 1] - 2.0f * cc[nt][3]) * LOG2E;
    }
    __syncthreads();

    float* dst = g_Ddiag + (size_t)b * (NDIAG * LSEQ);
    const int wi = tid >> 5, li = tid & 31;
    for (int dl = wi; dl < 127; dl += 8) {
        int lo = dl > 63 ? dl - 63 : 0;
        int hi = dl < 63 ? dl : 63;
        int dd = i0 + j0 + dl;
        for (int il = lo + li; il <= hi; il += 32) {
            dst[(size_t)dd * LSEQ + (i0 + il)] = Dt[il * 66 + (dl - il)];
        }
    }
}

/* ------------------------------------------------------------------ */
/* Kernel B: 2-CTA cluster per batch. Rank 0 = rows 1..512, rank 1 =  */
/* rows 513..1024. Boundary row R[512][*] streamed into rank 1's smem */
/* via st.shared::cluster + per-chunk mbarrier. One shfl per step     */
/* (diag operand = previous step's up operand).                        */
/* ------------------------------------------------------------------ */
#define CH      16
#define NCHUNK  66
#define KOFF    3
#define WPC     16
#define NROUNDS (KOFF * (WPC - 1) + NCHUNK)   /* 111 */

__global__ void __launch_bounds__(512) __cluster_dims__(2, 1, 1)
sdtw_pipeline_kernel(float* __restrict__ out) {
    const int b    = blockIdx.x >> 1;
    const int cons = blockIdx.x & 1;          /* cluster rank: 1 = consumer half */
    const int tid  = threadIdx.x;
    const int w    = tid >> 5;
    const int l    = tid & 31;

    __shared__ float    rb[WPC - 1][128];     /* intra-CTA boundary rings */
    __shared__ float    bnd[1060];            /* R[512][j] stream (consumer side) */
    __shared__ uint64_t mbar[NCHUNK];

    for (int e = tid; e < (WPC - 1) * 128; e += 512) ((float*)rb)[e] = BIGC;
    if (tid < NCHUNK) {
        uint32_t ma = smem_u32(&mbar[tid]);
        asm volatile("mbarrier.init.shared.b64 [%0], 1;" :: "r"(ma) : "memory");
    }
    __syncthreads();
    asm volatile("barrier.cluster.arrive.aligned;" ::: "memory");
    asm volatile("barrier.cluster.wait.aligned;"   ::: "memory");

    /* remote (rank 1) addresses for the producer */
    uint32_t bnd_rem, mbar_rem;
    {
        uint32_t bl = smem_u32(bnd), ml = smem_u32(mbar);
        asm("mapa.shared::cluster.u32 %0, %1, %2;" : "=r"(bnd_rem)  : "r"(bl), "r"(1));
        asm("mapa.shared::cluster.u32 %0, %1, %2;" : "=r"(mbar_rem) : "r"(ml), "r"(1));
    }

    float v1     = BIGC;   /* own value at step s-1 (left operand)          */
    float u_prev = (cons == 0 && w == 0 && l == 0) ? 0.0f : BIGC;  /* diag  */
    float result = 0.0f;

    const int R0 = cons * 512 + w * 32;       /* dd base; lane col = R0 + l */
    const float* dp = g_Ddiag + ((size_t)b << 21) + (size_t)R0 * LSEQ + (R0 + l);
    float*       rbw = (w < WPC - 1) ? rb[w] : rb[0];
    const float* rbr = (w > 0) ? rb[w - 1] : rb[0];

    for (int r = 0; r < NROUNDS; r++) {
        const int c = r - KOFF * w;
        if (c >= 0 && c < NCHUNK) {
            /* consumer warp0 waits for producer chunk c+2 (covers j<=16c+17) */
            if (cons && w == 0 && c + 2 < NCHUNK) {
                uint32_t ma = smem_u32(&mbar[c + 2]);
                uint32_t done;
                asm volatile(
                    "{.reg .pred p;\n\t"
                    "mbarrier.try_wait.parity.acquire.cta.shared::cta.b64 p, [%1], 0;\n\t"
                    "selp.b32 %0, 1, 0, p;}\n" : "=r"(done) : "r"(ma) : "memory");
                if (!done) {
                    asm volatile(
                        "{.reg .pred P1;\n\t"
                        "W_%=:\n\t"
                        "mbarrier.try_wait.parity.acquire.cta.shared::cta.b64 P1, [%0], 0, 0x989680;\n\t"
                        "@P1 bra D_%=;\n\t"
                        "bra W_%=;\n\t"
                        "D_%=:}\n" :: "r"(ma) : "memory");
                }
                asm volatile("fence.acq_rel.cluster;" ::: "memory");
            }

            const int sc = c * CH;
            float dv[CH];
            const float* dpc = dp + (size_t)sc * LSEQ;
#pragma unroll
            for (int k = 0; k < CH; k++) dv[k] = dpc[(size_t)k * LSEQ];

#pragma unroll
            for (int k = 0; k < CH; k++) {
                const int s = sc + k;
                float u = __shfl_up_sync(0xffffffffu, v1, 1);
                if (w == 0) {
                    if (cons) { float bk = bnd[s + 1]; if (l == 0) u = bk; }
                    else      { if (l == 0) u = BIGC; }
                } else {
                    if (l == 0) u = rbr[(s + 1) & 127];
                }
                float a = u_prev;
                bool act = (s >= l) && (s <= 1023 + l);
                if (act) {
                    float lf  = v1;
                    float mn1 = fminf(a, u);
                    float mx1 = fmaxf(a, u);
                    float m   = fminf(mn1, lf);
                    float M   = fmaxf(mx1, lf);
                    float med = fmaxf(mn1, fminf(mx1, lf));
                    float e   = 1.0f + ex2(m - med) + ex2(m - M);
                    float nv  = dv[k] + m - lg2(e);
                    if (l == 31) {
                        if (w < WPC - 1) {
                            rbw[(s - 30) & 127] = nv;
                        } else if (!cons) {
                            /* row 512 boundary -> consumer CTA smem */
                            asm volatile("st.shared::cluster.f32 [%0], %1;"
                                         :: "r"(bnd_rem + 4u * (uint32_t)(s - 30)), "f"(nv)
                                         : "memory");
                        } else if (s == 1054) {
                            result = nv;           /* R[1024][1024] */
                        }
                    }
                    v1 = nv;
                }
                u_prev = u;
            }

            /* producer signals chunk completion to consumer CTA */
            if (!cons && w == WPC - 1 && l == 31) {
                asm volatile("fence.acq_rel.cluster;" ::: "memory");
                asm volatile("mbarrier.arrive.shared::cluster.b64 _, [%0];"
                             :: "r"(mbar_rem + 8u * (uint32_t)c) : "memory");
            }
        }
        __syncthreads();
    }

    if (cons && w == WPC - 1 && l == 31) out[b] = result * LN2F;

    asm volatile("barrier.cluster.arrive.aligned;" ::: "memory");
    asm volatile("barrier.cluster.wait.aligned;"   ::: "memory");
}

/* ------------------------------------------------------------------ */
extern "C" void kernel_launch(void* const* d_in, const int* in_sizes, int n_in,
                              void* d_out, int out_size) {
    (void)in_sizes; (void)n_in; (void)out_size;
    const float* x = (const float*)d_in[0];
    const float* y = (const float*)d_in[1];
    float* out = (float*)d_out;

    dim3 gridA(256, NBATCH);
    compute_D_kernel<<<gridA, 256>>>(x, y);
    sdtw_pipeline_kernel<<<2 * NBATCH, 512>>>(out);
}

// round 4
// speedup vs baseline: 1.4681x; 1.4681x over previous
#include <cuda_runtime.h>
#include <math.h>
#include <cstdint>

#define LSEQ   1024
#define NBATCH 64
#define NCH    64
#define NDIAG  2048
#define BIGC   1.0e10f
#define LOG2E  1.4426950408889634f
#define LN2F   0.6931471805599453f

/* Diagonal-major scratch: Ddiag[b][dd][i], dd = i + j (0-based). */
__device__ float g_Ddiag[(size_t)NBATCH * NDIAG * LSEQ];

__device__ __forceinline__ float ex2(float z) {
    float r; asm("ex2.approx.f32 %0, %1;" : "=f"(r) : "f"(z)); return r;
}
__device__ __forceinline__ uint32_t f2tf32(float v) {
    uint32_t r; asm("cvt.rna.tf32.f32 %0, %1;" : "=r"(r) : "f"(v)); return r;
}

/* log2(1+t) - 1 = h(u), u = t-1 in [-1,1].  Degree-8 economized poly
   (Chebyshev expansion of ln(2+u), rho = 2-sqrt(3)), abs err < 4e-6. */
#define B1  0.72132839f
#define B2 -0.18031140f
#define B3  0.06035920f
#define B4 -0.02273770f
#define B5  0.00817517f
#define B6 -0.00324190f
#define B7  0.00261610f
#define B8 -0.00122670f

/* ------------------------------------------------------------------ */
/* Kernel A: D = (x2 + y2 - 2*x.y^T) * log2(e) via tf32 mma.sync,     */
/* written diagonal-major. tf32 cvt hoisted into the smem fill.        */
/* ------------------------------------------------------------------ */
__global__ void __launch_bounds__(256)
compute_D_kernel(const float* __restrict__ x, const float* __restrict__ y) {
    const int b  = blockIdx.y;
    const int ti = blockIdx.x >> 4;
    const int tj = blockIdx.x & 15;
    const int i0 = ti * 64, j0 = tj * 64;

    __shared__ float sbuf[2 * 64 * 68];    /* xs[64][68] | ys[64][68]; reused as Dt[64][66] */
    __shared__ float sx2[64], sy2[64];
    float* xs = sbuf;
    float* ys = sbuf + 64 * 68;

    const int tid = threadIdx.x;
    const float4* xb4 = (const float4*)(x + ((size_t)b * LSEQ + i0) * NCH);
    const float4* yb4 = (const float4*)(y + ((size_t)b * LSEQ + j0) * NCH);

#pragma unroll
    for (int k = 0; k < 4; k++) {
        int e = tid + 256 * k;
        int r = e >> 4, c4v = e & 15;
        float4 vx = xb4[r * 16 + c4v];
        float4 vy = yb4[r * 16 + c4v];
        vx.x = __uint_as_float(f2tf32(vx.x)); vx.y = __uint_as_float(f2tf32(vx.y));
        vx.z = __uint_as_float(f2tf32(vx.z)); vx.w = __uint_as_float(f2tf32(vx.w));
        vy.x = __uint_as_float(f2tf32(vy.x)); vy.y = __uint_as_float(f2tf32(vy.y));
        vy.z = __uint_as_float(f2tf32(vy.z)); vy.w = __uint_as_float(f2tf32(vy.w));
        *(float4*)&xs[r * 68 + c4v * 4] = vx;
        *(float4*)&ys[r * 68 + c4v * 4] = vy;
    }
    __syncthreads();

    if (tid < 64) {
        float s = 0.f;
#pragma unroll
        for (int c = 0; c < 64; c++) { float v = xs[tid * 68 + c]; s += v * v; }
        sx2[tid] = s;
    } else if (tid < 128) {
        int r = tid - 64;
        float s = 0.f;
#pragma unroll
        for (int c = 0; c < 64; c++) { float v = ys[r * 68 + c]; s += v * v; }
        sy2[r] = s;
    }
    __syncthreads();

    /* 8 warps: wr = warp&3 -> 16-row block, wc = warp>>2 -> 32-col block */
    const int wrp  = tid >> 5, lane = tid & 31;
    const int wr   = wrp & 3, wc = wrp >> 2;
    const int r4   = lane >> 2, c4 = lane & 3;
    const float* As = xs + (wr * 16) * 68;
    const float* Bs = ys + (wc * 32) * 68;

    float cc[4][4];
#pragma unroll
    for (int nt = 0; nt < 4; nt++)
#pragma unroll
        for (int q = 0; q < 4; q++) cc[nt][q] = 0.f;

#pragma unroll
    for (int k0 = 0; k0 < 64; k0 += 8) {
        uint32_t a0 = __float_as_uint(As[(r4)     * 68 + k0 + c4]);
        uint32_t a1 = __float_as_uint(As[(r4 + 8) * 68 + k0 + c4]);
        uint32_t a2 = __float_as_uint(As[(r4)     * 68 + k0 + c4 + 4]);
        uint32_t a3 = __float_as_uint(As[(r4 + 8) * 68 + k0 + c4 + 4]);
#pragma unroll
        for (int nt = 0; nt < 4; nt++) {
            uint32_t b0 = __float_as_uint(Bs[(nt * 8 + r4) * 68 + k0 + c4]);
            uint32_t b1 = __float_as_uint(Bs[(nt * 8 + r4) * 68 + k0 + c4 + 4]);
            asm volatile(
                "mma.sync.aligned.m16n8k8.row.col.f32.tf32.tf32.f32 "
                "{%0,%1,%2,%3}, {%4,%5,%6,%7}, {%8,%9}, {%0,%1,%2,%3};"
                : "+f"(cc[nt][0]), "+f"(cc[nt][1]), "+f"(cc[nt][2]), "+f"(cc[nt][3])
                : "r"(a0), "r"(a1), "r"(a2), "r"(a3), "r"(b0), "r"(b1));
        }
    }
    __syncthreads();                  /* xs/ys dead -> reuse as Dt */

    float* Dt = sbuf;                 /* [64][66] */
    const int row0 = wr * 16 + r4;
#pragma unroll
    for (int nt = 0; nt < 4; nt++) {
        int colb = wc * 32 + nt * 8 + 2 * c4;
        Dt[row0 * 66 + colb]           = (sx2[row0]     + sy2[colb]     - 2.0f * cc[nt][0]) * LOG2E;
        Dt[row0 * 66 + colb + 1]       = (sx2[row0]     + sy2[colb + 1] - 2.0f * cc[nt][1]) * LOG2E;
        Dt[(row0 + 8) * 66 + colb]     = (sx2[row0 + 8] + sy2[colb]     - 2.0f * cc[nt][2]) * LOG2E;
        Dt[(row0 + 8) * 66 + colb + 1] = (sx2[row0 + 8] + sy2[colb + 1] - 2.0f * cc[nt][3]) * LOG2E;
    }
    __syncthreads();

    float* dst = g_Ddiag + (size_t)b * (NDIAG * LSEQ);
    const int wi = tid >> 5, li = tid & 31;
    for (int dl = wi; dl < 127; dl += 8) {
        int lo = dl > 63 ? dl - 63 : 0;
        int hi = dl < 63 ? dl : 63;
        int dd = i0 + j0 + dl;
        for (int il = lo + li; il <= hi; il += 32) {
            dst[(size_t)dd * LSEQ + (i0 + il)] = Dt[il * 66 + (dl - il)];
        }
    }
}

/* ------------------------------------------------------------------ */
/* Kernel B: register-pipelined soft-DTW (intra-CTA, 32 warps).        */
/* Single shfl per step (diag = previous step's up operand), smem      */
/* boundary rings, double-buffered D prefetch (next chunk's LDGs       */
/* issued before computing the current chunk), polynomial log2 on the  */
/* FMA pipe (MUFU: 2 ex2 per cell only).                               */
/* ------------------------------------------------------------------ */
#define CH      16
#define NCHUNK  66                      /* 66*16 = 1056 >= 1055 local steps */
#define KOFF    3
#define NROUNDS (KOFF * 31 + NCHUNK)    /* 159 */

__global__ void __launch_bounds__(1024)
sdtw_pipeline_kernel(float* __restrict__ out) {
    const int b   = blockIdx.x;
    const int tid = threadIdx.x;
    const int w   = tid >> 5;
    const int l   = tid & 31;

    __shared__ float rb[31][128];       /* boundary rings: rb[w] fed by warp w lane 31 */

    for (int e = tid; e < 31 * 128; e += 1024) ((float*)rb)[e] = BIGC;
    __syncthreads();

    float v1     = BIGC;                            /* own value at step s-1 (left) */
    float u_prev = (w == 0 && l == 0) ? 0.0f : BIGC;/* diag operand                 */
    float result = 0.0f;

    const float* dp  = g_Ddiag + ((size_t)b << 21) + (size_t)(w * 32) * LSEQ + (w * 32 + l);
    float*       rbw = (w < 31) ? rb[w] : rb[0];
    const float* rbr = (w > 0) ? rb[w - 1] : rb[0];

    float dv[CH];
    if (w == 0) {                        /* warp 0 preloads its chunk 0 */
#pragma unroll
        for (int k = 0; k < CH; k++) dv[k] = dp[(size_t)k * LSEQ];
    }

    for (int r = 0; r < NROUNDS; r++) {
        const int c  = r - KOFF * w;
        const int cn = c + 1;

        /* prefetch next chunk (consumed next round) */
        float dn[CH];
        const bool pf = (cn >= 0) && (cn < NCHUNK);
        if (pf) {
            const float* dpn = dp + (size_t)(cn * CH) * LSEQ;
#pragma unroll
            for (int k = 0; k < CH; k++) dn[k] = dpn[(size_t)k * LSEQ];
        }

        if (c >= 0 && c < NCHUNK) {
            const int sc = c * CH;
#pragma unroll
            for (int k = 0; k < CH; k++) {
                const int s = sc + k;
                float rv = rbr[(s + 1) & 127];              /* broadcast LDS, off-chain */
                float u  = __shfl_up_sync(0xffffffffu, v1, 1);
                if (l == 0) u = (w == 0) ? BIGC : rv;
                float a = u_prev;
                bool act = (s >= l) && (s <= 1023 + l);
                if (act) {
                    float lf  = v1;
                    float mn1 = fminf(a, u);
                    float mx1 = fmaxf(a, u);
                    float m   = fminf(mn1, lf);
                    float M   = fmaxf(mx1, lf);
                    float med = fmaxf(mn1, fminf(mx1, lf));
                    float ea  = ex2(m - med);
                    float eb  = ex2(m - M);
                    float up  = ea + eb - 1.0f;             /* u in [-1,1] */
                    float h   = up * (B1 + up * (B2 + up * (B3 + up * (B4 +
                                up * (B5 + up * (B6 + up * (B7 + up * B8)))))));
                    float nv  = dv[k] + (m - 1.0f) - h;     /* d + m - log2(1+t) */
                    if (l == 31) {
                        if (w < 31) rbw[(s - 30) & 127] = nv;
                        else if (s == 1054) result = nv;    /* R[1024][1024] */
                    }
                    v1 = nv;
                }
                u_prev = u;
            }
        }

        if (pf) {
#pragma unroll
            for (int k = 0; k < CH; k++) dv[k] = dn[k];
        }
        __syncthreads();
    }

    if (w == 31 && l == 31) out[b] = result * LN2F;
}

/* ------------------------------------------------------------------ */
extern "C" void kernel_launch(void* const* d_in, const int* in_sizes, int n_in,
                              void* d_out, int out_size) {
    (void)in_sizes; (void)n_in; (void)out_size;
    const float* x = (const float*)d_in[0];
    const float* y = (const float*)d_in[1];
    float* out = (float*)d_out;

    dim3 gridA(256, NBATCH);
    compute_D_kernel<<<gridA, 256>>>(x, y);
    sdtw_pipeline_kernel<<<NBATCH, 1024>>>(out);
}

// round 5
// speedup vs baseline: 1.7374x; 1.1834x over previous
#include <cuda_runtime.h>
#include <math.h>
#include <cstdint>

#define LSEQ   1024
#define NBATCH 64
#define NCH    64
#define NDIAG  2048
#define BIGC   1.0e10f
#define LOG2E  1.4426950408889634f
#define LN2F   0.6931471805599453f

/* Diagonal-major scratch: Ddiag[b][dd][i], dd = i + j (0-based). */
__device__ float g_Ddiag[(size_t)NBATCH * NDIAG * LSEQ];

__device__ __forceinline__ float ex2(float z) {
    float r; asm("ex2.approx.f32 %0, %1;" : "=f"(r) : "f"(z)); return r;
}
__device__ __forceinline__ float lg2(float z) {
    float r; asm("lg2.approx.f32 %0, %1;" : "=f"(r) : "f"(z)); return r;
}
__device__ __forceinline__ uint32_t f2tf32(float v) {
    uint32_t r; asm("cvt.rna.tf32.f32 %0, %1;" : "=r"(r) : "f"(v)); return r;
}

/* ------------------------------------------------------------------ */
/* Kernel A: D = (x2 + y2 - 2*x.y^T) * log2(e) via tf32 mma.sync,     */
/* written diagonal-major. tf32 cvt hoisted into the smem fill.        */
/* ------------------------------------------------------------------ */
__global__ void __launch_bounds__(256)
compute_D_kernel(const float* __restrict__ x, const float* __restrict__ y) {
    const int b  = blockIdx.y;
    const int ti = blockIdx.x >> 4;
    const int tj = blockIdx.x & 15;
    const int i0 = ti * 64, j0 = tj * 64;

    __shared__ float sbuf[2 * 64 * 68];    /* xs[64][68] | ys[64][68]; reused as Dt[64][66] */
    __shared__ float sx2[64], sy2[64];
    float* xs = sbuf;
    float* ys = sbuf + 64 * 68;

    const int tid = threadIdx.x;
    const float4* xb4 = (const float4*)(x + ((size_t)b * LSEQ + i0) * NCH);
    const float4* yb4 = (const float4*)(y + ((size_t)b * LSEQ + j0) * NCH);

#pragma unroll
    for (int k = 0; k < 4; k++) {
        int e = tid + 256 * k;
        int r = e >> 4, c4v = e & 15;
        float4 vx = xb4[r * 16 + c4v];
        float4 vy = yb4[r * 16 + c4v];
        vx.x = __uint_as_float(f2tf32(vx.x)); vx.y = __uint_as_float(f2tf32(vx.y));
        vx.z = __uint_as_float(f2tf32(vx.z)); vx.w = __uint_as_float(f2tf32(vx.w));
        vy.x = __uint_as_float(f2tf32(vy.x)); vy.y = __uint_as_float(f2tf32(vy.y));
        vy.z = __uint_as_float(f2tf32(vy.z)); vy.w = __uint_as_float(f2tf32(vy.w));
        *(float4*)&xs[r * 68 + c4v * 4] = vx;
        *(float4*)&ys[r * 68 + c4v * 4] = vy;
    }
    __syncthreads();

    if (tid < 64) {
        float s = 0.f;
#pragma unroll
        for (int c = 0; c < 64; c++) { float v = xs[tid * 68 + c]; s += v * v; }
        sx2[tid] = s;
    } else if (tid < 128) {
        int r = tid - 64;
        float s = 0.f;
#pragma unroll
        for (int c = 0; c < 64; c++) { float v = ys[r * 68 + c]; s += v * v; }
        sy2[r] = s;
    }
    __syncthreads();

    /* 8 warps: wr = warp&3 -> 16-row block, wc = warp>>2 -> 32-col block */
    const int wrp  = tid >> 5, lane = tid & 31;
    const int wr   = wrp & 3, wc = wrp >> 2;
    const int r4   = lane >> 2, c4 = lane & 3;
    const float* As = xs + (wr * 16) * 68;
    const float* Bs = ys + (wc * 32) * 68;

    float cc[4][4];
#pragma unroll
    for (int nt = 0; nt < 4; nt++)
#pragma unroll
        for (int q = 0; q < 4; q++) cc[nt][q] = 0.f;

#pragma unroll
    for (int k0 = 0; k0 < 64; k0 += 8) {
        uint32_t a0 = __float_as_uint(As[(r4)     * 68 + k0 + c4]);
        uint32_t a1 = __float_as_uint(As[(r4 + 8) * 68 + k0 + c4]);
        uint32_t a2 = __float_as_uint(As[(r4)     * 68 + k0 + c4 + 4]);
        uint32_t a3 = __float_as_uint(As[(r4 + 8) * 68 + k0 + c4 + 4]);
#pragma unroll
        for (int nt = 0; nt < 4; nt++) {
            uint32_t b0 = __float_as_uint(Bs[(nt * 8 + r4) * 68 + k0 + c4]);
            uint32_t b1 = __float_as_uint(Bs[(nt * 8 + r4) * 68 + k0 + c4 + 4]);
            asm volatile(
                "mma.sync.aligned.m16n8k8.row.col.f32.tf32.tf32.f32 "
                "{%0,%1,%2,%3}, {%4,%5,%6,%7}, {%8,%9}, {%0,%1,%2,%3};"
                : "+f"(cc[nt][0]), "+f"(cc[nt][1]), "+f"(cc[nt][2]), "+f"(cc[nt][3])
                : "r"(a0), "r"(a1), "r"(a2), "r"(a3), "r"(b0), "r"(b1));
        }
    }
    __syncthreads();                  /* xs/ys dead -> reuse as Dt */

    float* Dt = sbuf;                 /* [64][66] */
    const int row0 = wr * 16 + r4;
#pragma unroll
    for (int nt = 0; nt < 4; nt++) {
        int colb = wc * 32 + nt * 8 + 2 * c4;
        Dt[row0 * 66 + colb]           = (sx2[row0]     + sy2[colb]     - 2.0f * cc[nt][0]) * LOG2E;
        Dt[row0 * 66 + colb + 1]       = (sx2[row0]     + sy2[colb + 1] - 2.0f * cc[nt][1]) * LOG2E;
        Dt[(row0 + 8) * 66 + colb]     = (sx2[row0 + 8] + sy2[colb]     - 2.0f * cc[nt][2]) * LOG2E;
        Dt[(row0 + 8) * 66 + colb + 1] = (sx2[row0 + 8] + sy2[colb + 1] - 2.0f * cc[nt][3]) * LOG2E;
    }
    __syncthreads();

    float* dst = g_Ddiag + (size_t)b * (NDIAG * LSEQ);
    const int wi = tid >> 5, li = tid & 31;
    for (int dl = wi; dl < 127; dl += 8) {
        int lo = dl > 63 ? dl - 63 : 0;
        int hi = dl < 63 ? dl : 63;
        int dd = i0 + j0 + dl;
        for (int il = lo + li; il <= hi; il += 32) {
            dst[(size_t)dd * LSEQ + (i0 + il)] = Dt[il * 66 + (dl - il)];
        }
    }
}

/* ------------------------------------------------------------------ */
/* Kernel B: register-pipelined soft-DTW (intra-CTA, 32 warps).        */
/* Single shfl per step, smem boundary rings, double-buffered D        */
/* prefetch, lg2-based softmin (3 MUFU, minimal issue slots), fully    */
/* UNGUARDED step body: inactive lanes compute harmless junk (values   */
/* stay ~1e10; ex2 of huge negatives is exactly 0; junk only flows     */
/* into other inactive lanes / unread ring slots).                     */
/* ------------------------------------------------------------------ */
#define CH      16
#define NCHUNK  66                      /* 66*16 = 1056 >= 1055 local steps */
#define KOFF    3
#define NROUNDS (KOFF * 31 + NCHUNK)    /* 159 */

__global__ void __launch_bounds__(1024)
sdtw_pipeline_kernel(float* __restrict__ out) {
    const int b   = blockIdx.x;
    const int tid = threadIdx.x;
    const int w   = tid >> 5;
    const int l   = tid & 31;

    __shared__ float rb[31][128];       /* boundary rings: rb[w] fed by warp w lane 31 */

    for (int e = tid; e < 31 * 128; e += 1024) ((float*)rb)[e] = BIGC;
    __syncthreads();

    float v1     = BIGC;                            /* own value at step s-1 (left) */
    float u_prev = (w == 0 && l == 0) ? 0.0f : BIGC;/* diag operand                 */
    float result = 0.0f;

    const float* dp  = g_Ddiag + ((size_t)b << 21) + (size_t)(w * 32) * LSEQ + (w * 32 + l);
    float*       rbw = (w < 31) ? rb[w] : rb[0];
    const float* rbr = (w > 0) ? rb[w - 1] : rb[0];

    float dv[CH];
    if (w == 0) {                        /* warp 0 preloads its chunk 0 */
#pragma unroll
        for (int k = 0; k < CH; k++) dv[k] = dp[(size_t)k * LSEQ];
    }

    for (int r = 0; r < NROUNDS; r++) {
        const int c  = r - KOFF * w;
        const int cn = c + 1;

        /* prefetch next chunk (consumed next round) */
        float dn[CH];
        const bool pf = (cn >= 0) && (cn < NCHUNK);
        if (pf) {
            const float* dpn = dp + (size_t)(cn * CH) * LSEQ;
#pragma unroll
            for (int k = 0; k < CH; k++) dn[k] = dpn[(size_t)k * LSEQ];
        }

        if (c >= 0 && c < NCHUNK) {
            const int sc = c * CH;
#pragma unroll
            for (int k = 0; k < CH; k++) {
                const int s = sc + k;
                float rv = rbr[(s + 1) & 127];              /* broadcast LDS */
                float u  = __shfl_up_sync(0xffffffffu, v1, 1);
                if (l == 0) u = (w == 0) ? BIGC : rv;
                float a   = u_prev;
                float lf  = v1;
                float mn1 = fminf(a, u);
                float mx1 = fmaxf(a, u);
                float m   = fminf(mn1, lf);
                float M   = fmaxf(mx1, lf);
                float med = fmaxf(mn1, fminf(mx1, lf));
                float e   = 1.0f + ex2(m - med) + ex2(m - M);
                float nv  = dv[k] + m - lg2(e);
                if (l == 31) {
                    if (w < 31) rbw[(s - 30) & 127] = nv;
                    else if (s == 1054) result = nv;        /* R[1024][1024] */
                }
                v1     = nv;
                u_prev = u;
            }
        }

        if (pf) {
#pragma unroll
            for (int k = 0; k < CH; k++) dv[k] = dn[k];
        }
        __syncthreads();
    }

    if (w == 31 && l == 31) out[b] = result * LN2F;
}

/* ------------------------------------------------------------------ */
extern "C" void kernel_launch(void* const* d_in, const int* in_sizes, int n_in,
                              void* d_out, int out_size) {
    (void)in_sizes; (void)n_in; (void)out_size;
    const float* x = (const float*)d_in[0];
    const float* y = (const float*)d_in[1];
    float* out = (float*)d_out;

    dim3 gridA(256, NBATCH);
    compute_D_kernel<<<gridA, 256>>>(x, y);
    sdtw_pipeline_kernel<<<NBATCH, 1024>>>(out);
}

// round 6
// speedup vs baseline: 1.8346x; 1.0560x over previous
#include <cuda_runtime.h>
#include <math.h>
#include <cstdint>

#define LSEQ   1024
#define NBATCH 64
#define NCH    64
#define NSTEP  1056          /* steps per strip: 1024 + 31 + pad */
#define BIGC   1.0e10f
#define LOG2E  1.4426950408889634f
#define LN2F   0.6931471805599453f

/* Warp-step-major scratch: g_Dw[b][w][s][q], q = i & 63 (w = i>>6),
   value = D[i][jj]*log2(e) with jj = s - (q>>1). 277 MB. Slots with
   jj outside [0,1023] are never written and stay 0 (harmless). */
__device__ float g_Dw[(size_t)NBATCH * 16 * NSTEP * 64];

__device__ __forceinline__ float ex2(float z) {
    float r; asm("ex2.approx.f32 %0, %1;" : "=f"(r) : "f"(z)); return r;
}
__device__ __forceinline__ float lg2(float z) {
    float r; asm("lg2.approx.f32 %0, %1;" : "=f"(r) : "f"(z)); return r;
}
__device__ __forceinline__ uint32_t f2tf32(float v) {
    uint32_t r; asm("cvt.rna.tf32.f32 %0, %1;" : "=r"(r) : "f"(v)); return r;
}
/* softmin in base-2 domain: -log2(2^-a + 2^-u + 2^-lf) */
__device__ __forceinline__ float softmin3(float a, float u, float lf) {
    float mn1 = fminf(a, u);
    float mx1 = fmaxf(a, u);
    float m   = fminf(mn1, lf);
    float M   = fmaxf(mx1, lf);
    float med = fmaxf(mn1, fminf(mx1, lf));
    float e   = 1.0f + ex2(m - med) + ex2(m - M);
    return m - lg2(e);
}

/* ------------------------------------------------------------------ */
/* Kernel A: D = (x2 + y2 - 2*x.y^T) * log2(e) via tf32 mma.sync,     */
/* written into the warp-step-major layout g_Dw.                       */
/* ------------------------------------------------------------------ */
__global__ void __launch_bounds__(256)
compute_D_kernel(const float* __restrict__ x, const float* __restrict__ y) {
    const int b  = blockIdx.y;
    const int ti = blockIdx.x >> 4;
    const int tj = blockIdx.x & 15;
    const int i0 = ti * 64, j0 = tj * 64;

    __shared__ float sbuf[2 * 64 * 68];    /* xs[64][68] | ys[64][68]; reused as Dt_T[64][67] */
    __shared__ float sx2[64], sy2[64];
    float* xs = sbuf;
    float* ys = sbuf + 64 * 68;

    const int tid = threadIdx.x;
    const float4* xb4 = (const float4*)(x + ((size_t)b * LSEQ + i0) * NCH);
    const float4* yb4 = (const float4*)(y + ((size_t)b * LSEQ + j0) * NCH);

#pragma unroll
    for (int k = 0; k < 4; k++) {
        int e = tid + 256 * k;
        int r = e >> 4, c4v = e & 15;
        float4 vx = xb4[r * 16 + c4v];
        float4 vy = yb4[r * 16 + c4v];
        vx.x = __uint_as_float(f2tf32(vx.x)); vx.y = __uint_as_float(f2tf32(vx.y));
        vx.z = __uint_as_float(f2tf32(vx.z)); vx.w = __uint_as_float(f2tf32(vx.w));
        vy.x = __uint_as_float(f2tf32(vy.x)); vy.y = __uint_as_float(f2tf32(vy.y));
        vy.z = __uint_as_float(f2tf32(vy.z)); vy.w = __uint_as_float(f2tf32(vy.w));
        *(float4*)&xs[r * 68 + c4v * 4] = vx;
        *(float4*)&ys[r * 68 + c4v * 4] = vy;
    }
    __syncthreads();

    if (tid < 64) {
        float s = 0.f;
#pragma unroll
        for (int c = 0; c < 64; c++) { float v = xs[tid * 68 + c]; s += v * v; }
        sx2[tid] = s;
    } else if (tid < 128) {
        int r = tid - 64;
        float s = 0.f;
#pragma unroll
        for (int c = 0; c < 64; c++) { float v = ys[r * 68 + c]; s += v * v; }
        sy2[r] = s;
    }
    __syncthreads();

    const int wrp  = tid >> 5, lane = tid & 31;
    const int wr   = wrp & 3, wc = wrp >> 2;
    const int r4   = lane >> 2, c4 = lane & 3;
    const float* As = xs + (wr * 16) * 68;
    const float* Bs = ys + (wc * 32) * 68;

    float cc[4][4];
#pragma unroll
    for (int nt = 0; nt < 4; nt++)
#pragma unroll
        for (int q = 0; q < 4; q++) cc[nt][q] = 0.f;

#pragma unroll
    for (int k0 = 0; k0 < 64; k0 += 8) {
        uint32_t a0 = __float_as_uint(As[(r4)     * 68 + k0 + c4]);
        uint32_t a1 = __float_as_uint(As[(r4 + 8) * 68 + k0 + c4]);
        uint32_t a2 = __float_as_uint(As[(r4)     * 68 + k0 + c4 + 4]);
        uint32_t a3 = __float_as_uint(As[(r4 + 8) * 68 + k0 + c4 + 4]);
#pragma unroll
        for (int nt = 0; nt < 4; nt++) {
            uint32_t b0 = __float_as_uint(Bs[(nt * 8 + r4) * 68 + k0 + c4]);
            uint32_t b1 = __float_as_uint(Bs[(nt * 8 + r4) * 68 + k0 + c4 + 4]);
            asm volatile(
                "mma.sync.aligned.m16n8k8.row.col.f32.tf32.tf32.f32 "
                "{%0,%1,%2,%3}, {%4,%5,%6,%7}, {%8,%9}, {%0,%1,%2,%3};"
                : "+f"(cc[nt][0]), "+f"(cc[nt][1]), "+f"(cc[nt][2]), "+f"(cc[nt][3])
                : "r"(a0), "r"(a1), "r"(a2), "r"(a3), "r"(b0), "r"(b1));
        }
    }
    __syncthreads();                  /* xs/ys dead -> reuse as Dt_T */

    float* Dt = sbuf;                 /* Dt_T[jl][il], stride 67 */
    const int row0 = wr * 16 + r4;
#pragma unroll
    for (int nt = 0; nt < 4; nt++) {
        int colb = wc * 32 + nt * 8 + 2 * c4;
        Dt[colb * 67 + row0]           = (sx2[row0]     + sy2[colb]     - 2.0f * cc[nt][0]) * LOG2E;
        Dt[(colb + 1) * 67 + row0]     = (sx2[row0]     + sy2[colb + 1] - 2.0f * cc[nt][1]) * LOG2E;
        Dt[colb * 67 + row0 + 8]       = (sx2[row0 + 8] + sy2[colb]     - 2.0f * cc[nt][2]) * LOG2E;
        Dt[(colb + 1) * 67 + row0 + 8] = (sx2[row0 + 8] + sy2[colb + 1] - 2.0f * cc[nt][3]) * LOG2E;
    }
    __syncthreads();

    /* write to warp-step-major layout: row s -> 64 contiguous floats   */
    /* lane li supplies q = 2li, 2li+1 (jl = so - li).                  */
    const size_t gbase = ((size_t)(b * 16 + ti) * NSTEP) * 64;
    for (int so = wrp; so < 95; so += 8) {
        int s  = j0 + so;
        int lo = so > 63 ? so - 63 : 0;
        int hi = so < 31 ? so : 31;
        if (lane >= lo && lane <= hi) {
            int jl = so - lane;
            float2 pv = make_float2(Dt[jl * 67 + 2 * lane], Dt[jl * 67 + 2 * lane + 1]);
            *(float2*)(g_Dw + gbase + (size_t)s * 64 + 2 * lane) = pv;
        }
    }
}

/* ------------------------------------------------------------------ */
/* Kernel B: 2 rows per lane, 16 warps. Lane l owns rows 64w+2l{+1}.  */
/* One shfl + one ring op per 2 cells. Double-buffered float2 D       */
/* prefetch. Unguarded body (junk cells self-quench at ~1e10).         */
/* ------------------------------------------------------------------ */
#define CH      16
#define NCHUNK  66
#define KOFF    3
#define NWARP   16
#define NROUNDS (KOFF * (NWARP - 1) + NCHUNK)   /* 111 */

__global__ void __launch_bounds__(512)
sdtw_pipeline_kernel(float* __restrict__ out) {
    const int b   = blockIdx.x;
    const int tid = threadIdx.x;
    const int w   = tid >> 5;
    const int l   = tid & 31;

    __shared__ float rb[NWARP - 1][128];   /* ring w fed by warp w lane 31 (row 64w+64) */

    for (int e = tid; e < (NWARP - 1) * 128; e += 512) ((float*)rb)[e] = BIGC;
    __syncthreads();

    float v1_0 = BIGC, v1_1 = BIGC;                    /* left values rows r0, r1   */
    float u0_prev = (w == 0 && l == 0) ? 0.0f : BIGC;  /* diag for r0               */
    float result  = 0.0f;

    const float* dpB = g_Dw + ((size_t)(b * NWARP + w) * NSTEP) * 64 + 2 * l;
    float*       rbw = (w < NWARP - 1) ? rb[w] : rb[0];
    const float* rbr = (w > 0) ? rb[w - 1] : rb[0];

    float2 dv[CH];
    if (w == 0) {
#pragma unroll
        for (int k = 0; k < CH; k++) dv[k] = *(const float2*)(dpB + (size_t)k * 64);
    }

    for (int r = 0; r < NROUNDS; r++) {
        const int c  = r - KOFF * w;
        const int cn = c + 1;

        float2 dn[CH];
        const bool pf = (cn >= 0) && (cn < NCHUNK);
        if (pf) {
            const float* dpn = dpB + (size_t)(cn * CH) * 64;
#pragma unroll
            for (int k = 0; k < CH; k++) dn[k] = *(const float2*)(dpn + (size_t)k * 64);
        }

        if (c >= 0 && c < NCHUNK) {
            const int sc = c * CH;
#pragma unroll
            for (int k = 0; k < CH; k++) {
                const int s = sc + k;
                float rv = rbr[(s + 1) & 127];              /* broadcast LDS */
                float u0 = __shfl_up_sync(0xffffffffu, v1_1, 1);
                if (l == 0) u0 = (w == 0) ? BIGC : rv;
                /* cell (r0, j): diag=u0_prev, up=u0, left=v1_0 */
                float nv0 = dv[k].x + softmin3(u0_prev, u0, v1_0);
                /* cell (r1, j): diag=v1_0(old), up=nv0, left=v1_1 */
                float nv1 = dv[k].y + softmin3(v1_0, nv0, v1_1);
                if (l == 31) {
                    if (w < NWARP - 1) rbw[(s - 30) & 127] = nv1;
                    else if (s == 1054) result = nv1;       /* R[1024][1024] */
                }
                v1_0    = nv0;
                v1_1    = nv1;
                u0_prev = u0;
            }
        }

        if (pf) {
#pragma unroll
            for (int k = 0; k < CH; k++) dv[k] = dn[k];
        }
        __syncthreads();
    }

    if (w == NWARP - 1 && l == 31) out[b] = result * LN2F;
}

/* ------------------------------------------------------------------ */
extern "C" void kernel_launch(void* const* d_in, const int* in_sizes, int n_in,
                              void* d_out, int out_size) {
    (void)in_sizes; (void)n_in; (void)out_size;
    const float* x = (const float*)d_in[0];
    const float* y = (const float*)d_in[1];
    float* out = (float*)d_out;

    dim3 gridA(256, NBATCH);
    compute_D_kernel<<<gridA, 256>>>(x, y);
    sdtw_pipeline_kernel<<<NBATCH, 512>>>(out);
}